// round 3
// baseline (speedup 1.0000x reference)
#include <cuda_runtime.h>
#include <cuda_bf16.h>
#include <math_constants.h>

#define NN 100000
#define EE 1600000
#define DD 192
#define HH 4
#define DHH 48
#define D3 576
#define DFF 384

// ---------------- scratch (device globals: no allocation allowed) ----------------
__device__ int g_is_int32;
__device__ int g_prefix[NN];
__device__ int g_T;
__device__ int g_order[NN];     // order[i] = rank(i)
__device__ int g_inv[NN];       // inv[rank] = i
__device__ int g_rowstart[NN + 1];
__device__ float g_h[(size_t)NN * DD];
__device__ float g_hn[(size_t)NN * DD];
__device__ float g_q[(size_t)NN * DD];
__device__ float g_k[(size_t)NN * DD];
__device__ float g_v[(size_t)NN * DD];
__device__ float g_agg[(size_t)NN * DD];
__device__ float g_proj[(size_t)NN * DD];
__device__ float g_t1[(size_t)NN * DD];
__device__ float g_hn2[(size_t)NN * DD];
__device__ float g_mlp1[(size_t)NN * DFF];

__device__ __forceinline__ int read_mask(const void* mask, int i) {
    if (g_is_int32)
        return ((const int*)mask)[i] != 0;
    return ((const unsigned char*)mask)[i] != 0;
}

// ---------------- mask dtype detection ----------------
// Device-side init (graph-capture safe: no host-sourced memcpys).
__global__ void init_flag_kernel() { g_is_int32 = 1; }

// View buffer as N/4 uint32 words (in-bounds for both layouts). Packed-bool
// data yields words like 0x01010101 (>1) with overwhelming probability; int32
// 0/1 data yields only 0/1 words. Any word >1 => uint8 layout.
__global__ void detect_mask_kernel(const unsigned* __restrict__ m) {
    int i = blockIdx.x * blockDim.x + threadIdx.x;
    if (i >= NN / 4) return;
    if (m[i] > 1u) atomicExch(&g_is_int32, 0);
}

// ---------------- permutation: inclusive scan of train_mask ----------------
__global__ void scan_mask_kernel(const void* __restrict__ mask) {
    __shared__ int sh[1024];
    __shared__ int carry;
    int tid = threadIdx.x;
    if (tid == 0) carry = 0;
    __syncthreads();
    for (int base = 0; base < NN; base += 1024) {
        int i = base + tid;
        int v = (i < NN) ? read_mask(mask, i) : 0;
        sh[tid] = v;
        __syncthreads();
        for (int off = 1; off < 1024; off <<= 1) {
            int t = (tid >= off) ? sh[tid - off] : 0;
            __syncthreads();
            sh[tid] += t;
            __syncthreads();
        }
        if (i < NN) g_prefix[i] = carry + sh[tid];
        __syncthreads();
        if (tid == 0) carry += sh[1023];
        __syncthreads();
    }
    if (tid == 0) g_T = carry;
}

__global__ void ranks_kernel(const void* __restrict__ mask) {
    int i = blockIdx.x * blockDim.x + threadIdx.x;
    if (i >= NN) return;
    int inc = g_prefix[i];
    int T = g_T;
    int r = read_mask(mask, i) ? (inc - 1) : (T + i - inc);
    g_order[i] = r;
    g_inv[r] = i;
}

// h[i] = x[order[i]]
__global__ void gather_h_kernel(const float* __restrict__ x) {
    int idx = blockIdx.x * blockDim.x + threadIdx.x;
    if (idx >= NN * DD) return;
    int i = idx / DD;
    int d = idx - i * DD;
    g_h[idx] = x[(size_t)g_order[i] * DD + d];
}

// t1[j] = x[j] + proj[inv[j]]
__global__ void residual_unperm_kernel(const float* __restrict__ x) {
    int idx = blockIdx.x * blockDim.x + threadIdx.x;
    if (idx >= NN * DD) return;
    int j = idx / DD;
    int d = idx - j * DD;
    g_t1[idx] = x[idx] + g_proj[(size_t)g_inv[j] * DD + d];
}

// ---------------- layernorm: one warp per row ----------------
__global__ void ln_kernel(const float* __restrict__ in, const float* __restrict__ g,
                          const float* __restrict__ b, float* __restrict__ out) {
    int row = blockIdx.x * 8 + (threadIdx.x >> 5);
    if (row >= NN) return;
    int lane = threadIdx.x & 31;
    const float* p = in + (size_t)row * DD;
    float vals[6];
    float s = 0.f;
#pragma unroll
    for (int j = 0; j < 6; j++) { vals[j] = p[lane + j * 32]; s += vals[j]; }
#pragma unroll
    for (int off = 16; off > 0; off >>= 1) s += __shfl_xor_sync(0xffffffffu, s, off);
    float mu = s * (1.f / DD);
    float vs = 0.f;
#pragma unroll
    for (int j = 0; j < 6; j++) { float d = vals[j] - mu; vs += d * d; }
#pragma unroll
    for (int off = 16; off > 0; off >>= 1) vs += __shfl_xor_sync(0xffffffffu, vs, off);
    float r = rsqrtf(vs * (1.f / DD) + 1e-5f);
    float* o = out + (size_t)row * DD;
#pragma unroll
    for (int j = 0; j < 6; j++) {
        int c = lane + j * 32;
        o[c] = (vals[j] - mu) * r * g[c] + b[c];
    }
}

// ---------------- CSR row offsets from sorted dst ----------------
__global__ void rowstart_kernel(const int* __restrict__ dst) {
    int e = blockIdx.x * blockDim.x + threadIdx.x;
    if (e >= EE) return;
    int cur = dst[e];
    int prev = (e == 0) ? -1 : dst[e - 1];
    for (int n = prev + 1; n <= cur; n++) g_rowstart[n] = e;
    if (e == EE - 1) {
        for (int n = cur + 1; n <= NN; n++) g_rowstart[n] = EE;
    }
}

// ---------------- graph attention: one warp per destination node ----------------
// lane layout: head = lane>>3 (4 heads), sub = lane&7, 6 contiguous elems per lane
__global__ void attn_kernel(const int* __restrict__ src) {
    int warp = (blockIdx.x * blockDim.x + threadIdx.x) >> 5;
    if (warp >= NN) return;
    int lane = threadIdx.x & 31;
    int off = (lane >> 3) * DHH + (lane & 7) * 6;
    const float* qp = g_q + (size_t)warp * DD + off;
    float qr[6];
#pragma unroll
    for (int j = 0; j < 6; j++) qr[j] = qp[j];

    int s0 = g_rowstart[warp];
    int s1 = g_rowstart[warp + 1];
    const float coef = 0.14433756729740643f; // 1/sqrt(48)
    float m = -CUDART_INF_F;
    float l = 0.f;
    float acc[6] = {0.f, 0.f, 0.f, 0.f, 0.f, 0.f};

    for (int e = s0; e < s1; e++) {
        int sn = src[e];
        const float* kp = g_k + (size_t)sn * DD + off;
        const float* vp = g_v + (size_t)sn * DD + off;
        float partial = 0.f;
        float kv[6];
#pragma unroll
        for (int j = 0; j < 6; j++) { kv[j] = kp[j]; partial += qr[j] * kv[j]; }
        partial += __shfl_xor_sync(0xffffffffu, partial, 1);
        partial += __shfl_xor_sync(0xffffffffu, partial, 2);
        partial += __shfl_xor_sync(0xffffffffu, partial, 4);
        float sscore = partial * coef;
        float mn = fmaxf(m, sscore);
        float es = expf(sscore - mn);
        float sc = expf(m - mn); // first iter: exp(-inf)=0
        l = l * sc + es;
#pragma unroll
        for (int j = 0; j < 6; j++) acc[j] = acc[j] * sc + es * vp[j];
        m = mn;
    }
    float invl = (s1 > s0) ? (1.f / l) : 0.f;
    float* op = g_agg + (size_t)warp * DD + off;
#pragma unroll
    for (int j = 0; j < 6; j++) op[j] = acc[j] * invl;
}

// ---------------- SGEMM: C[MxNc] = A[MxK] @ B[KxNc] + bias, with epilogues ----------------
// BM=128, BN=64, BK=16, 256 threads, each thread 8x4 outputs
#define BM 128
#define BN 64
#define BK 16
// mode: 0 = plain, 1 = gelu(exact), 2 = residual add, 3 = qkv scatter
__global__ void gemm_kernel(const float* __restrict__ A, const float* __restrict__ B,
                            const float* __restrict__ bias, float* __restrict__ out,
                            const float* __restrict__ res,
                            float* __restrict__ q, float* __restrict__ k, float* __restrict__ v,
                            int M, int K, int Nc, int mode) {
    __shared__ float As[BK][BM];
    __shared__ float Bs[BK][BN];
    int tid = threadIdx.x;
    int tx = tid & 15;  // n direction
    int ty = tid >> 4;  // m direction
    int m0 = blockIdx.x * BM;
    int n0 = blockIdx.y * BN;

    float acc[8][4];
#pragma unroll
    for (int a = 0; a < 8; a++)
#pragma unroll
        for (int bq = 0; bq < 4; bq++) acc[a][bq] = 0.f;

    for (int k0 = 0; k0 < K; k0 += BK) {
#pragma unroll
        for (int i = 0; i < 2; i++) {
            int idx = tid + i * 256;          // 0..511
            int row = idx >> 2;               // 0..127
            int cv = (idx & 3) * 4;           // 0,4,8,12
            int gm = m0 + row;
            float4 av = (gm < M) ? *(const float4*)(A + (size_t)gm * K + k0 + cv)
                                 : make_float4(0.f, 0.f, 0.f, 0.f);
            As[cv + 0][row] = av.x;
            As[cv + 1][row] = av.y;
            As[cv + 2][row] = av.z;
            As[cv + 3][row] = av.w;
        }
        {
            int row = tid >> 4;               // 0..15
            int cv = (tid & 15) * 4;          // 0..60
            float4 bv = *(const float4*)(B + (size_t)(k0 + row) * Nc + n0 + cv);
            *(float4*)&Bs[row][cv] = bv;
        }
        __syncthreads();
#pragma unroll
        for (int kk = 0; kk < BK; kk++) {
            float af[8];
#pragma unroll
            for (int j = 0; j < 8; j++) af[j] = As[kk][ty * 8 + j];
            float4 bv = *(float4*)&Bs[kk][tx * 4];
            float bf[4] = {bv.x, bv.y, bv.z, bv.w};
#pragma unroll
            for (int jm = 0; jm < 8; jm++)
#pragma unroll
                for (int jn = 0; jn < 4; jn++) acc[jm][jn] += af[jm] * bf[jn];
        }
        __syncthreads();
    }

#pragma unroll
    for (int jm = 0; jm < 8; jm++) {
        int m = m0 + ty * 8 + jm;
        if (m >= M) continue;
#pragma unroll
        for (int jn = 0; jn < 4; jn++) {
            int n = n0 + tx * 4 + jn;
            float val = acc[jm][jn] + bias[n];
            if (mode == 0) {
                out[(size_t)m * Nc + n] = val;
            } else if (mode == 1) {
                out[(size_t)m * Nc + n] = val * normcdff(val);
            } else if (mode == 2) {
                out[(size_t)m * Nc + n] = val + res[(size_t)m * Nc + n];
            } else {
                int hh = n / 144;
                int r = n - hh * 144;
                int w = r / DHH;
                int dd = r - w * DHH;
                float* dp = (w == 0) ? q : (w == 1) ? k : v;
                dp[(size_t)m * DD + hh * DHH + dd] = val;
            }
        }
    }
}

// ---------------- launch ----------------
static inline void* sym(const void* s) {
    void* p = nullptr;
    cudaGetSymbolAddress(&p, s);
    return p;
}

extern "C" void kernel_launch(void* const* d_in, const int* in_sizes, int n_in,
                              void* d_out, int out_size) {
    const float* x = (const float*)d_in[0];
    const void* mask = d_in[1];
    const int* src = (const int*)d_in[2];
    const int* dst = (const int*)d_in[3];
    const float* ln1_g = (const float*)d_in[4];
    const float* ln1_b = (const float*)d_in[5];
    const float* Wqkv = (const float*)d_in[6];
    const float* bqkv = (const float*)d_in[7];
    const float* Wout = (const float*)d_in[8];
    const float* bout = (const float*)d_in[9];
    const float* ln2_g = (const float*)d_in[10];
    const float* ln2_b = (const float*)d_in[11];
    const float* W1 = (const float*)d_in[12];
    const float* b1 = (const float*)d_in[13];
    const float* W2 = (const float*)d_in[14];
    const float* b2 = (const float*)d_in[15];
    float* out = (float*)d_out;

    float* h = (float*)sym(g_h);
    float* hn = (float*)sym(g_hn);
    float* q = (float*)sym(g_q);
    float* k = (float*)sym(g_k);
    float* v = (float*)sym(g_v);
    float* agg = (float*)sym(g_agg);
    float* proj = (float*)sym(g_proj);
    float* t1 = (float*)sym(g_t1);
    float* hn2 = (float*)sym(g_hn2);
    float* mlp1 = (float*)sym(g_mlp1);

    // 0. mask dtype detection (device-side init; graph-capture safe)
    init_flag_kernel<<<1, 1>>>();
    detect_mask_kernel<<<(NN / 4 + 255) / 256, 256>>>((const unsigned*)mask);

    // 1. permutation
    scan_mask_kernel<<<1, 1024>>>(mask);
    ranks_kernel<<<(NN + 255) / 256, 256>>>(mask);

    // 2. gather h = x[order]
    gather_h_kernel<<<(NN * DD + 255) / 256, 256>>>(x);

    // 3. LN1
    ln_kernel<<<(NN + 7) / 8, 256>>>(h, ln1_g, ln1_b, hn);

    // 4. CSR offsets
    rowstart_kernel<<<(EE + 255) / 256, 256>>>(dst);

    // 5. QKV GEMM with scatter epilogue
    {
        dim3 grid((NN + BM - 1) / BM, D3 / BN);
        gemm_kernel<<<grid, 256>>>(hn, Wqkv, bqkv, nullptr, nullptr, q, k, v,
                                   NN, DD, D3, 3);
    }

    // 6. graph attention (online softmax, warp per node)
    attn_kernel<<<(NN * 32 + 255) / 256, 256>>>(src);

    // 7. out-projection
    {
        dim3 grid((NN + BM - 1) / BM, DD / BN);
        gemm_kernel<<<grid, 256>>>(agg, Wout, bout, proj, nullptr, nullptr, nullptr, nullptr,
                                   NN, DD, DD, 0);
    }

    // 8. residual + inverse permutation: t1[j] = x[j] + proj[inv[j]]
    residual_unperm_kernel<<<(NN * DD + 255) / 256, 256>>>(x);

    // 9. LN2
    ln_kernel<<<(NN + 7) / 8, 256>>>(t1, ln2_g, ln2_b, hn2);

    // 10. MLP up + exact GELU
    {
        dim3 grid((NN + BM - 1) / BM, DFF / BN);
        gemm_kernel<<<grid, 256>>>(hn2, W1, b1, mlp1, nullptr, nullptr, nullptr, nullptr,
                                   NN, DD, DFF, 1);
    }

    // 11. MLP down + residual -> output
    {
        dim3 grid((NN + BM - 1) / BM, DD / BN);
        gemm_kernel<<<grid, 256>>>(mlp1, W2, b2, out, t1, nullptr, nullptr, nullptr,
                                   NN, DFF, DD, 2);
    }
}

// round 4
// speedup vs baseline: 1.6544x; 1.6544x over previous
#include <cuda_runtime.h>
#include <cuda_bf16.h>
#include <math_constants.h>

#define NN 100000
#define EE 1600000
#define DD 192
#define HH 4
#define DHH 48
#define D3 576
#define DFF 384
#define NB 98   // number of 1024-wide scan blocks

// ---------------- scratch ----------------
__device__ int g_is_int32;
__device__ int g_prefix[NN];
__device__ int g_bsum[NB];
__device__ int g_boff[NB];
__device__ int g_T;
__device__ int g_order[NN];
__device__ int g_inv[NN];
__device__ int g_rowstart[NN + 1];
__device__ float g_hn[(size_t)NN * DD];
__device__ float g_q[(size_t)NN * DD];
__device__ __nv_bfloat16 g_kb[(size_t)NN * DD];
__device__ __nv_bfloat16 g_vb[(size_t)NN * DD];
__device__ float g_agg[(size_t)NN * DD];
__device__ float g_proj[(size_t)NN * DD];
__device__ float g_t1[(size_t)NN * DD];
__device__ float g_hn2[(size_t)NN * DD];
__device__ float g_mlp1[(size_t)NN * DFF];

__device__ __forceinline__ int read_mask(const void* mask, int i) {
    if (g_is_int32) return ((const int*)mask)[i] != 0;
    return ((const unsigned char*)mask)[i] != 0;
}

__device__ __forceinline__ unsigned f2tf32(float f) {
    unsigned r;
    asm("cvt.rna.tf32.f32 %0, %1;" : "=r"(r) : "f"(f));
    return r;
}

// ---------------- mask dtype detection ----------------
__global__ void init_flag_kernel() { g_is_int32 = 1; }
__global__ void detect_mask_kernel(const unsigned* __restrict__ m) {
    int i = blockIdx.x * blockDim.x + threadIdx.x;
    if (i >= NN / 4) return;
    if (m[i] > 1u) atomicExch(&g_is_int32, 0);
}

// ---------------- multi-block scan ----------------
__global__ void blockscan_kernel(const void* __restrict__ mask) {
    int tid = threadIdx.x;
    int i = blockIdx.x * 1024 + tid;
    int v = (i < NN) ? read_mask(mask, i) : 0;
    int lane = tid & 31, wid = tid >> 5;
    int s = v;
#pragma unroll
    for (int off = 1; off < 32; off <<= 1) {
        int t = __shfl_up_sync(0xffffffffu, s, off);
        if (lane >= off) s += t;
    }
    __shared__ int wsum[32];
    if (lane == 31) wsum[wid] = s;
    __syncthreads();
    if (wid == 0) {
        int ws = wsum[lane];
#pragma unroll
        for (int off = 1; off < 32; off <<= 1) {
            int t = __shfl_up_sync(0xffffffffu, ws, off);
            if (lane >= off) ws += t;
        }
        wsum[lane] = ws;
    }
    __syncthreads();
    int incl = s + (wid > 0 ? wsum[wid - 1] : 0);
    if (i < NN) g_prefix[i] = incl;
    if (tid == 1023) g_bsum[blockIdx.x] = incl;
}

__global__ void scan_sums_kernel() {
    int tid = threadIdx.x; // 128 threads
    int v = (tid < NB) ? g_bsum[tid] : 0;
    int lane = tid & 31, wid = tid >> 5;
    int s = v;
#pragma unroll
    for (int off = 1; off < 32; off <<= 1) {
        int t = __shfl_up_sync(0xffffffffu, s, off);
        if (lane >= off) s += t;
    }
    __shared__ int wsum[4];
    if (lane == 31) wsum[wid] = s;
    __syncthreads();
    int add = 0;
    for (int w = 0; w < wid; w++) add += wsum[w];
    int incl = s + add;
    if (tid < NB) g_boff[tid] = incl - v;
    if (tid == NB - 1) g_T = incl;
}

__global__ void ranks_kernel(const void* __restrict__ mask) {
    int i = blockIdx.x * blockDim.x + threadIdx.x;
    if (i >= NN) return;
    int inc = g_prefix[i] + g_boff[i >> 10];
    int T = g_T;
    int r = read_mask(mask, i) ? (inc - 1) : (T + i - inc);
    g_order[i] = r;
    g_inv[r] = i;
}

// t1[j] = x[j] + proj[inv[j]]
__global__ void residual_unperm_kernel(const float* __restrict__ x) {
    int idx = blockIdx.x * blockDim.x + threadIdx.x;
    if (idx >= NN * DD) return;
    int j = idx / DD;
    int d = idx - j * DD;
    g_t1[idx] = x[idx] + g_proj[(size_t)g_inv[j] * DD + d];
}

// ---------------- layernorm (optional row gather) ----------------
__global__ void ln_kernel(const float* __restrict__ in, const float* __restrict__ g,
                          const float* __restrict__ b, float* __restrict__ out,
                          const int* __restrict__ order) {
    int row = blockIdx.x * 8 + (threadIdx.x >> 5);
    if (row >= NN) return;
    int lane = threadIdx.x & 31;
    int srow = order ? order[row] : row;
    const float* p = in + (size_t)srow * DD;
    float vals[6];
    float s = 0.f;
#pragma unroll
    for (int j = 0; j < 6; j++) { vals[j] = p[lane + j * 32]; s += vals[j]; }
#pragma unroll
    for (int off = 16; off > 0; off >>= 1) s += __shfl_xor_sync(0xffffffffu, s, off);
    float mu = s * (1.f / DD);
    float vs = 0.f;
#pragma unroll
    for (int j = 0; j < 6; j++) { float d = vals[j] - mu; vs += d * d; }
#pragma unroll
    for (int off = 16; off > 0; off >>= 1) vs += __shfl_xor_sync(0xffffffffu, vs, off);
    float r = rsqrtf(vs * (1.f / DD) + 1e-5f);
    float* o = out + (size_t)row * DD;
#pragma unroll
    for (int j = 0; j < 6; j++) {
        int c = lane + j * 32;
        o[c] = (vals[j] - mu) * r * g[c] + b[c];
    }
}

// ---------------- CSR row offsets ----------------
__global__ void rowstart_kernel(const int* __restrict__ dst) {
    int e = blockIdx.x * blockDim.x + threadIdx.x;
    if (e >= EE) return;
    int cur = dst[e];
    int prev = (e == 0) ? -1 : dst[e - 1];
    for (int n = prev + 1; n <= cur; n++) g_rowstart[n] = e;
    if (e == EE - 1) {
        for (int n = cur + 1; n <= NN; n++) g_rowstart[n] = EE;
    }
}

// ---------------- graph attention (bf16 k/v) ----------------
__global__ void attn_kernel(const int* __restrict__ src) {
    int warp = (blockIdx.x * blockDim.x + threadIdx.x) >> 5;
    if (warp >= NN) return;
    int lane = threadIdx.x & 31;
    int off = (lane >> 3) * DHH + (lane & 7) * 6;
    const float* qp = g_q + (size_t)warp * DD + off;
    float qr[6];
#pragma unroll
    for (int j = 0; j < 6; j++) qr[j] = qp[j];

    int s0 = g_rowstart[warp];
    int s1 = g_rowstart[warp + 1];
    const float coef = 0.14433756729740643f;
    float m = -CUDART_INF_F;
    float l = 0.f;
    float acc[6] = {0.f, 0.f, 0.f, 0.f, 0.f, 0.f};

    for (int e = s0; e < s1; e++) {
        int sn = src[e];
        const __nv_bfloat162* kp = (const __nv_bfloat162*)(g_kb + (size_t)sn * DD + off);
        const __nv_bfloat162* vp = (const __nv_bfloat162*)(g_vb + (size_t)sn * DD + off);
        float kv[6], vv[6];
#pragma unroll
        for (int j = 0; j < 3; j++) {
            float2 kf = __bfloat1622float2(kp[j]);
            float2 vf = __bfloat1622float2(vp[j]);
            kv[2 * j] = kf.x; kv[2 * j + 1] = kf.y;
            vv[2 * j] = vf.x; vv[2 * j + 1] = vf.y;
        }
        float partial = 0.f;
#pragma unroll
        for (int j = 0; j < 6; j++) partial += qr[j] * kv[j];
        partial += __shfl_xor_sync(0xffffffffu, partial, 1);
        partial += __shfl_xor_sync(0xffffffffu, partial, 2);
        partial += __shfl_xor_sync(0xffffffffu, partial, 4);
        float sscore = partial * coef;
        float mn = fmaxf(m, sscore);
        float es = __expf(sscore - mn);
        float sc = __expf(m - mn);
        l = l * sc + es;
#pragma unroll
        for (int j = 0; j < 6; j++) acc[j] = acc[j] * sc + es * vv[j];
        m = mn;
    }
    float invl = (s1 > s0) ? (1.f / l) : 0.f;
    float* op = g_agg + (size_t)warp * DD + off;
#pragma unroll
    for (int j = 0; j < 6; j++) op[j] = acc[j] * invl;
}

// ---------------- tf32 tensor-core GEMM ----------------
// C[MxNc] = A[MxK] @ B[KxNc] + bias; BM=128, BN=64, BK=16; 256 threads (8 warps 4x2)
// warp tile 32x32 = 2 (m16) x 4 (n8) mma tiles
#define BM 128
#define BN 64
#define BK 16
#define ASTRIDE 132  // BM+4: bank-spread, 16B-aligned
#define BSTRIDE 68   // BN+4

__device__ __forceinline__ void mma_tf32(float& c0, float& c1, float& c2, float& c3,
                                         unsigned a0, unsigned a1, unsigned a2, unsigned a3,
                                         unsigned b0, unsigned b1) {
    asm volatile(
        "mma.sync.aligned.m16n8k8.row.col.f32.tf32.tf32.f32 "
        "{%0,%1,%2,%3}, {%4,%5,%6,%7}, {%8,%9}, {%0,%1,%2,%3};"
        : "+f"(c0), "+f"(c1), "+f"(c2), "+f"(c3)
        : "r"(a0), "r"(a1), "r"(a2), "r"(a3), "r"(b0), "r"(b1));
}

// mode: 0 plain, 1 gelu, 2 residual, 3 qkv scatter (q fp32, k/v bf16)
__global__ void gemm_kernel(const float* __restrict__ A, const float* __restrict__ B,
                            const float* __restrict__ bias, float* __restrict__ out,
                            const float* __restrict__ res,
                            int M, int K, int Nc, int mode) {
    __shared__ unsigned As[BK][ASTRIDE];
    __shared__ unsigned Bs[BK][BSTRIDE];
    int tid = threadIdx.x;
    int lane = tid & 31;
    int wid = tid >> 5;
    int warp_m = wid & 3;   // 4 warps over M (32 rows each)
    int warp_n = wid >> 2;  // 2 warps over N (32 cols each)
    int m0 = blockIdx.x * BM;
    int n0 = blockIdx.y * BN;
    int gid = lane >> 2;    // 0..7
    int tig = lane & 3;     // 0..3

    float acc[2][4][4];
#pragma unroll
    for (int mt = 0; mt < 2; mt++)
#pragma unroll
        for (int nt = 0; nt < 4; nt++)
#pragma unroll
            for (int j = 0; j < 4; j++) acc[mt][nt][j] = 0.f;

    for (int k0 = 0; k0 < K; k0 += BK) {
        // load A tile: 128x16 fp32 -> tf32
#pragma unroll
        for (int i = 0; i < 2; i++) {
            int idx = tid + i * 256;
            int row = idx >> 2;
            int cv = (idx & 3) * 4;
            int gm = m0 + row;
            float4 av = (gm < M) ? *(const float4*)(A + (size_t)gm * K + k0 + cv)
                                 : make_float4(0.f, 0.f, 0.f, 0.f);
            As[cv + 0][row] = f2tf32(av.x);
            As[cv + 1][row] = f2tf32(av.y);
            As[cv + 2][row] = f2tf32(av.z);
            As[cv + 3][row] = f2tf32(av.w);
        }
        // load B tile: 16x64 fp32 -> tf32
        {
            int row = tid >> 4;
            int cv = (tid & 15) * 4;
            float4 bv = *(const float4*)(B + (size_t)(k0 + row) * Nc + n0 + cv);
            Bs[row][cv + 0] = f2tf32(bv.x);
            Bs[row][cv + 1] = f2tf32(bv.y);
            Bs[row][cv + 2] = f2tf32(bv.z);
            Bs[row][cv + 3] = f2tf32(bv.w);
        }
        __syncthreads();

        unsigned a[2][2][4]; // [mt][ks][4]
#pragma unroll
        for (int mt = 0; mt < 2; mt++) {
            int r = warp_m * 32 + mt * 16 + gid;
#pragma unroll
            for (int ks = 0; ks < 2; ks++) {
                int c = ks * 8 + tig;
                a[mt][ks][0] = As[c][r];
                a[mt][ks][1] = As[c][r + 8];
                a[mt][ks][2] = As[c + 4][r];
                a[mt][ks][3] = As[c + 4][r + 8];
            }
        }
        unsigned b[4][2][2]; // [nt][ks][2]
#pragma unroll
        for (int nt = 0; nt < 4; nt++) {
            int n = warp_n * 32 + nt * 8 + gid;
#pragma unroll
            for (int ks = 0; ks < 2; ks++) {
                int c = ks * 8 + tig;
                b[nt][ks][0] = Bs[c][n];
                b[nt][ks][1] = Bs[c + 4][n];
            }
        }
#pragma unroll
        for (int ks = 0; ks < 2; ks++)
#pragma unroll
            for (int mt = 0; mt < 2; mt++)
#pragma unroll
                for (int nt = 0; nt < 4; nt++)
                    mma_tf32(acc[mt][nt][0], acc[mt][nt][1], acc[mt][nt][2], acc[mt][nt][3],
                             a[mt][ks][0], a[mt][ks][1], a[mt][ks][2], a[mt][ks][3],
                             b[nt][ks][0], b[nt][ks][1]);
        __syncthreads();
    }

    // epilogue
#pragma unroll
    for (int mt = 0; mt < 2; mt++) {
#pragma unroll
        for (int nt = 0; nt < 4; nt++) {
#pragma unroll
            for (int half = 0; half < 2; half++) {
                int m = m0 + warp_m * 32 + mt * 16 + gid + half * 8;
                if (m >= M) continue;
#pragma unroll
                for (int j = 0; j < 2; j++) {
                    int n = n0 + warp_n * 32 + nt * 8 + 2 * tig + j;
                    float val = acc[mt][nt][half * 2 + j] + bias[n];
                    if (mode == 0) {
                        out[(size_t)m * Nc + n] = val;
                    } else if (mode == 1) {
                        out[(size_t)m * Nc + n] = val * normcdff(val);
                    } else if (mode == 2) {
                        out[(size_t)m * Nc + n] = val + res[(size_t)m * Nc + n];
                    } else {
                        int hh = n / 144;
                        int r = n - hh * 144;
                        int w = r / DHH;
                        int dd = r - w * DHH;
                        size_t o = (size_t)m * DD + hh * DHH + dd;
                        if (w == 0) g_q[o] = val;
                        else if (w == 1) g_kb[o] = __float2bfloat16_rn(val);
                        else g_vb[o] = __float2bfloat16_rn(val);
                    }
                }
            }
        }
    }
}

// ---------------- launch ----------------
static inline void* sym(const void* s) {
    void* p = nullptr;
    cudaGetSymbolAddress(&p, s);
    return p;
}

extern "C" void kernel_launch(void* const* d_in, const int* in_sizes, int n_in,
                              void* d_out, int out_size) {
    const float* x = (const float*)d_in[0];
    const void* mask = d_in[1];
    const int* src = (const int*)d_in[2];
    const int* dst = (const int*)d_in[3];
    const float* ln1_g = (const float*)d_in[4];
    const float* ln1_b = (const float*)d_in[5];
    const float* Wqkv = (const float*)d_in[6];
    const float* bqkv = (const float*)d_in[7];
    const float* Wout = (const float*)d_in[8];
    const float* bout = (const float*)d_in[9];
    const float* ln2_g = (const float*)d_in[10];
    const float* ln2_b = (const float*)d_in[11];
    const float* W1 = (const float*)d_in[12];
    const float* b1 = (const float*)d_in[13];
    const float* W2 = (const float*)d_in[14];
    const float* b2 = (const float*)d_in[15];
    float* out = (float*)d_out;

    float* hn = (float*)sym(g_hn);
    float* agg = (float*)sym(g_agg);
    float* proj = (float*)sym(g_proj);
    float* t1 = (float*)sym(g_t1);
    float* hn2 = (float*)sym(g_hn2);
    float* mlp1 = (float*)sym(g_mlp1);
    int* order = (int*)sym(g_order);

    // 0. mask dtype detection
    init_flag_kernel<<<1, 1>>>();
    detect_mask_kernel<<<(NN / 4 + 255) / 256, 256>>>((const unsigned*)mask);

    // 1. permutation (multi-block scan)
    blockscan_kernel<<<NB, 1024>>>(mask);
    scan_sums_kernel<<<1, 128>>>();
    ranks_kernel<<<(NN + 255) / 256, 256>>>(mask);

    // 2. LN1 fused with gather: hn[i] = LN(x[order[i]])
    ln_kernel<<<(NN + 7) / 8, 256>>>(x, ln1_g, ln1_b, hn, order);

    // 3. CSR offsets
    rowstart_kernel<<<(EE + 255) / 256, 256>>>(dst);

    // 4. QKV GEMM (scatter epilogue: q fp32, k/v bf16)
    {
        dim3 grid((NN + BM - 1) / BM, D3 / BN);
        gemm_kernel<<<grid, 256>>>(hn, Wqkv, bqkv, nullptr, nullptr, NN, DD, D3, 3);
    }

    // 5. graph attention
    attn_kernel<<<(NN * 32 + 255) / 256, 256>>>(src);

    // 6. out-projection
    {
        dim3 grid((NN + BM - 1) / BM, DD / BN);
        gemm_kernel<<<grid, 256>>>(agg, Wout, bout, proj, nullptr, NN, DD, DD, 0);
    }

    // 7. residual + inverse permutation
    residual_unperm_kernel<<<(NN * DD + 255) / 256, 256>>>(x);

    // 8. LN2
    ln_kernel<<<(NN + 7) / 8, 256>>>(t1, ln2_g, ln2_b, hn2, nullptr);

    // 9. MLP up + GELU
    {
        dim3 grid((NN + BM - 1) / BM, DFF / BN);
        gemm_kernel<<<grid, 256>>>(hn2, W1, b1, mlp1, nullptr, NN, DD, DFF, 1);
    }

    // 10. MLP down + residual -> out
    {
        dim3 grid((NN + BM - 1) / BM, DD / BN);
        gemm_kernel<<<grid, 256>>>(mlp1, W2, b2, out, t1, NN, DFF, DD, 2);
    }
}